// round 9
// baseline (speedup 1.0000x reference)
#include <cuda_runtime.h>
#include <math_constants.h>
#include <cstdint>

#define NN    10000   // nodes
#define D     128     // feature dim
#define TOPK  8
#define DEG   32
#define OUTCH 128
#define INCH  9       // K+1
#define KS    9       // kernel size
#define XOUT  120     // D - K
#define GRID  740     // 148 SMs x 5 CTAs

// Prepacked weight pairs for packed-f32x2 conv:
//   k=0..4 (even-x set):  (w_{2k}, w_{2k+1}) with w9 := 0
//   k=5..9 (odd-x  set):  j=k-5: j==0 -> (0, w0) ; else (w_{2j-1}, w_{2j})
// Layout [c][k][o]: a warp's 32 consecutive o read 256B contiguous (L1-hot).
__device__ float2 g_wpre[INCH][10][OUTCH];

__global__ void prep_weights_kernel(const float* __restrict__ cw)
{
    int idx = blockIdx.x * blockDim.x + threadIdx.x;
    if (idx >= INCH * 10 * OUTCH) return;
    int o = idx % OUTCH;
    int k = (idx / OUTCH) % 10;
    int c = idx / (OUTCH * 10);
    const float* w = cw + (size_t)o * (INCH * KS) + c * KS;   // w[0..8]
    float2 v;
    if (k < 5) {
        v.x = w[2 * k];
        v.y = (2 * k + 1 < KS) ? w[2 * k + 1] : 0.0f;
    } else {
        int j = k - 5;
        if (j == 0) { v.x = 0.0f;          v.y = w[0];     }
        else        { v.x = w[2 * j - 1];  v.y = w[2 * j]; }
    }
    g_wpre[c][k][o] = v;
}

__device__ __forceinline__ unsigned long long ffma2(unsigned long long a,
                                                    unsigned long long b,
                                                    unsigned long long c)
{
    unsigned long long d;
    asm("fma.rn.f32x2 %0, %1, %2, %3;" : "=l"(d) : "l"(a), "l"(b), "l"(c));
    return d;
}

// -------- per-feature-column top-8 into sel buffer --------
__device__ __forceinline__ void topk_build(const float* __restrict__ nf,
                                           const int* __restrict__ nbr,
                                           int m, int n, int d,
                                           float sel[INCH][D])
{
    float tk[TOPK];
    #pragma unroll
    for (int s = 0; s < TOPK; s++) tk[s] = -CUDART_INF_F;

    #pragma unroll
    for (int j0 = 0; j0 < DEG; j0 += 8) {
        float v[8];
        #pragma unroll
        for (int u = 0; u < 8; u++) {
            int j = j0 + u;
            v[u] = (j < m) ? nf[(size_t)nbr[j] * D + d] : -CUDART_INF_F;
        }
        #pragma unroll
        for (int u = 0; u < 8; u++) {
            float x = v[u];
            #pragma unroll
            for (int s = 0; s < TOPK; s++) {
                float hi = fmaxf(tk[s], x);
                x        = fminf(tk[s], x);
                tk[s]    = hi;
            }
        }
    }
    // torch zero-pads missing neighbors before topk
    for (int z = m; z < TOPK; z++) {
        float x = 0.0f;
        #pragma unroll
        for (int s = 0; s < TOPK; s++) {
            float hi = fmaxf(tk[s], x);
            x        = fminf(tk[s], x);
            tk[s]    = hi;
        }
    }
    sel[0][d] = nf[(size_t)n * D + d];
    #pragma unroll
    for (int s = 0; s < TOPK; s++) sel[1 + s][d] = tk[s];
}

// Persistent kernel: all threads conv; next node's adjacency scan is
// software-pipelined into the conv chunks (loads at chunk start, compaction
// at chunk end), so the scan phase vanishes behind FFMA2 work.
__global__ __launch_bounds__(128, 5)
void lgcl_pers_kernel(const float* __restrict__ nf,
                      const int*   __restrict__ adj,
                      const float* __restrict__ cb,
                      float*       __restrict__ out)
{
    __shared__ __align__(16) float sel[2][INCH][D];
    __shared__ int s_nbr[2][DEG];
    __shared__ int s_cnt[2];

    const int tid = threadIdx.x;
    const float bias = cb[tid];

    // ---- prologue: scan + topk for first node ----
    int n = blockIdx.x;
    if (tid == 0) s_cnt[0] = 0;
    __syncthreads();
    {
        const int4* row4 = reinterpret_cast<const int4*>(adj + (size_t)n * NN);
        for (int i = tid; i < NN / 4; i += 128) {
            int4 v = row4[i];
            if (v.x | v.y | v.z | v.w) {
                if (v.x) s_nbr[0][atomicAdd(&s_cnt[0], 1)] = 4 * i + 0;
                if (v.y) s_nbr[0][atomicAdd(&s_cnt[0], 1)] = 4 * i + 1;
                if (v.z) s_nbr[0][atomicAdd(&s_cnt[0], 1)] = 4 * i + 2;
                if (v.w) s_nbr[0][atomicAdd(&s_cnt[0], 1)] = 4 * i + 3;
            }
        }
    }
    __syncthreads();
    topk_build(nf, s_nbr[0], s_cnt[0], n, tid, sel[0]);

    int cur = 0;
    for (; n < NN; n += GRID) {
        const int nn = n + GRID;
        const bool have_next = (nn < NN);
        const int nxt = cur ^ 1;

        if (tid == 0) s_cnt[nxt] = 0;
        __syncthreads();   // sel[cur] ready (prev topk), cnt reset visible

        // ================= conv(n) + interleaved scan(nn) =================
        const int o = tid;
        float* op = out + ((size_t)n * OUTCH + o) * XOUT;
        const int4* row4n = reinterpret_cast<const int4*>(adj + (size_t)nn * NN);

        #pragma unroll
        for (int ch = 0; ch < 5; ch++) {
            const int cb0 = ch * 24;

            // -- issue next-node scan loads for this chunk (latency hidden) --
            int4 sv[4];
            int  si[4];
            #pragma unroll
            for (int q = 0; q < 4; q++) {
                int i = tid + (ch * 4 + q) * 128;
                si[q] = i;
                sv[q] = (have_next && i < NN / 4) ? row4n[i]
                                                  : make_int4(0, 0, 0, 0);
            }

            // -- conv chunk: 24 outputs via packed f32x2, tap-paired --
            unsigned long long acc[24];
            #pragma unroll
            for (int u = 0; u < 24; u++) acc[u] = 0ull;

            for (int c = 0; c < INCH; c++) {
                unsigned long long W[10];
                #pragma unroll
                for (int k = 0; k < 10; k++)
                    W[k] = *reinterpret_cast<const unsigned long long*>(&g_wpre[c][k][o]);

                const unsigned long long* Prow =
                    reinterpret_cast<const unsigned long long*>(&sel[cur][c][0]);

                #pragma unroll
                for (int g = 0; g < 24; g += 8) {      // 8 x = 4 x-pairs
                    const int e0 = (cb0 + g) >> 1;
                    unsigned long long P[8];
                    #pragma unroll
                    for (int i = 0; i < 8; i++) P[i] = Prow[e0 + i];
                    #pragma unroll
                    for (int j = 0; j < 4; j++) {
                        #pragma unroll
                        for (int k = 0; k < 5; k++) {
                            acc[g + 2 * j]     = ffma2(P[j + k], W[k],     acc[g + 2 * j]);
                            acc[g + 2 * j + 1] = ffma2(P[j + k], W[5 + k], acc[g + 2 * j + 1]);
                        }
                    }
                }
            }

            // -- compact the scan loads issued at chunk start --
            #pragma unroll
            for (int q = 0; q < 4; q++) {
                int4 v = sv[q];
                if (v.x | v.y | v.z | v.w) {
                    int e = 4 * si[q];
                    if (v.x) s_nbr[nxt][atomicAdd(&s_cnt[nxt], 1)] = e + 0;
                    if (v.y) s_nbr[nxt][atomicAdd(&s_cnt[nxt], 1)] = e + 1;
                    if (v.z) s_nbr[nxt][atomicAdd(&s_cnt[nxt], 1)] = e + 2;
                    if (v.w) s_nbr[nxt][atomicAdd(&s_cnt[nxt], 1)] = e + 3;
                }
            }

            // -- horizontal add + bias, vectorized store --
            #pragma unroll
            for (int u = 0; u < 24; u += 4) {
                float2 a0 = *reinterpret_cast<float2*>(&acc[u + 0]);
                float2 a1 = *reinterpret_cast<float2*>(&acc[u + 1]);
                float2 a2 = *reinterpret_cast<float2*>(&acc[u + 2]);
                float2 a3 = *reinterpret_cast<float2*>(&acc[u + 3]);
                float4 r = make_float4(a0.x + a0.y + bias,
                                       a1.x + a1.y + bias,
                                       a2.x + a2.y + bias,
                                       a3.x + a3.y + bias);
                *reinterpret_cast<float4*>(op + cb0 + u) = r;
            }
        }

        __syncthreads();   // scan(nn) complete everywhere

        // ---- topk + sel build for next node ----
        if (have_next)
            topk_build(nf, s_nbr[nxt], s_cnt[nxt], nn, tid, sel[nxt]);

        cur = nxt;
    }
}

extern "C" void kernel_launch(void* const* d_in, const int* in_sizes, int n_in,
                              void* d_out, int out_size)
{
    const float* nf  = (const float*)d_in[0];   // [10000, 128]
    const int*   adj = (const int*)  d_in[1];   // [10000, 10000]
    const float* cw  = (const float*)d_in[2];   // [128, 9, 9]
    const float* cb  = (const float*)d_in[3];   // [128]
    float*       out = (float*)d_out;           // [10000, 128, 120]

    prep_weights_kernel<<<(INCH * 10 * OUTCH + 127) / 128, 128>>>(cw);
    lgcl_pers_kernel<<<GRID, 128>>>(nf, adj, cb, out);
}

// round 13
// speedup vs baseline: 1.1840x; 1.1840x over previous
#include <cuda_runtime.h>
#include <math_constants.h>
#include <cstdint>

#define NN    10000   // nodes
#define D     128     // feature dim
#define TOPK  8
#define DEG   32
#define OUTCH 128
#define INCH  9       // K+1
#define KS    9       // kernel size
#define XOUT  120     // D - K

// Prepacked weight pairs for packed-f32x2 conv:
//   k=0..4 (even-x set):  (w_{2k}, w_{2k+1}) with w9 := 0
//   k=5..9 (odd-x  set):  j=k-5: j==0 -> (0, w0) ; else (w_{2j-1}, w_{2j})
// Layout [c][k][o]: a warp's 32 consecutive o read 256B contiguous (L1-hot).
__device__ float2 g_wpre[INCH][10][OUTCH];

__global__ void prep_weights_kernel(const float* __restrict__ cw)
{
    int idx = blockIdx.x * blockDim.x + threadIdx.x;
    if (idx >= INCH * 10 * OUTCH) return;
    int o = idx % OUTCH;
    int k = (idx / OUTCH) % 10;
    int c = idx / (OUTCH * 10);
    const float* w = cw + (size_t)o * (INCH * KS) + c * KS;   // w[0..8]
    float2 v;
    if (k < 5) {
        v.x = w[2 * k];
        v.y = (2 * k + 1 < KS) ? w[2 * k + 1] : 0.0f;
    } else {
        int j = k - 5;
        if (j == 0) { v.x = 0.0f;          v.y = w[0];     }
        else        { v.x = w[2 * j - 1];  v.y = w[2 * j]; }
    }
    g_wpre[c][k][o] = v;
}

__device__ __forceinline__ unsigned long long ffma2(unsigned long long a,
                                                    unsigned long long b,
                                                    unsigned long long c)
{
    unsigned long long d;
    asm("fma.rn.f32x2 %0, %1, %2, %3;" : "=l"(d) : "l"(a), "l"(b), "l"(c));
    return d;
}

__global__ __launch_bounds__(128, 6)
void lgcl_fused_kernel(const float* __restrict__ nf,
                       const int*   __restrict__ adj,
                       const float* __restrict__ cb,
                       float*       __restrict__ out)
{
    __shared__ __align__(16) float sel[INCH][D];  // row 0 = self, 1..8 = top-8 desc
    __shared__ int nbrs[DEG];
    __shared__ int cnt;

    const int n   = blockIdx.x;
    const int tid = threadIdx.x;     // 128 threads

    if (tid == 0) cnt = 0;
    if (tid < DEG) nbrs[tid] = 0;
    __syncthreads();

    // ---- Phase A: scan adjacency row (MLP 4), compact neighbor indices ----
    {
        const int4* row4 = reinterpret_cast<const int4*>(adj + (size_t)n * NN);
        #pragma unroll
        for (int it = 0; it < 5; it++) {
            int4 v[4];
            int  ii[4];
            #pragma unroll
            for (int q = 0; q < 4; q++) {
                int i = tid + it * 512 + q * 128;
                ii[q] = i;
                v[q] = (i < NN / 4) ? row4[i] : make_int4(0, 0, 0, 0);
            }
            #pragma unroll
            for (int q = 0; q < 4; q++) {
                int4 w = v[q];
                if (w.x | w.y | w.z | w.w) {
                    int e = 4 * ii[q];
                    if (w.x) nbrs[atomicAdd(&cnt, 1)] = e + 0;
                    if (w.y) nbrs[atomicAdd(&cnt, 1)] = e + 1;
                    if (w.z) nbrs[atomicAdd(&cnt, 1)] = e + 2;
                    if (w.w) nbrs[atomicAdd(&cnt, 1)] = e + 3;
                }
            }
        }
    }
    __syncthreads();
    const int m = cnt;   // number of real neighbors (<= 32)

    // ---- Phase B: per-feature-column top-8 (all 32 gather loads in flight) ----
    {
        const int d = tid;           // column index, 0..127
        float v[DEG];
        #pragma unroll
        for (int j = 0; j < DEG; j++)
            v[j] = (j < m) ? nf[(size_t)nbrs[j] * D + d] : -CUDART_INF_F;

        float tk[TOPK];
        #pragma unroll
        for (int s = 0; s < TOPK; s++) tk[s] = -CUDART_INF_F;

        #pragma unroll
        for (int j = 0; j < DEG; j++) {
            float x = v[j];
            #pragma unroll
            for (int s = 0; s < TOPK; s++) {
                float hi = fmaxf(tk[s], x);
                x        = fminf(tk[s], x);
                tk[s]    = hi;
            }
        }
        // torch zero-pads missing neighbors before topk: insert (8-m) zeros
        for (int z = m; z < TOPK; z++) {
            float x = 0.0f;
            #pragma unroll
            for (int s = 0; s < TOPK; s++) {
                float hi = fmaxf(tk[s], x);
                x        = fminf(tk[s], x);
                tk[s]    = hi;
            }
        }

        sel[0][d] = nf[(size_t)n * D + d];
        #pragma unroll
        for (int s = 0; s < TOPK; s++) sel[1 + s][d] = tk[s];
    }
    __syncthreads();

    // ---- Phase C: Conv1d via packed fma.rn.f32x2, chunks of 12 outputs ----
    // out[o][x] (x even) = sum_c sum_k (w2k,w2k+1).(win[x+2k],win[x+2k+1]); w9=0
    // odd x uses the same window pairs with the shifted weight set W[5..9].
    {
        const int o = tid;           // output channel
        const float bias = cb[o];
        float* op = out + ((size_t)n * OUTCH + o) * XOUT;

        for (int cb0 = 0; cb0 < XOUT; cb0 += 12) {      // 10 chunks of 12 x
            unsigned long long acc[12];
            #pragma unroll
            for (int u = 0; u < 12; u++) acc[u] = 0ull;

            for (int c = 0; c < INCH; c++) {
                unsigned long long W[10];
                #pragma unroll
                for (int k = 0; k < 10; k++)
                    W[k] = *reinterpret_cast<const unsigned long long*>(&g_wpre[c][k][o]);

                const unsigned long long* Prow =
                    reinterpret_cast<const unsigned long long*>(&sel[c][0]);
                const int e0 = cb0 >> 1;

                unsigned long long P[10];
                #pragma unroll
                for (int i = 0; i < 10; i++) P[i] = Prow[e0 + i];

                // group of 8 outputs (x-pairs j=0..3)
                #pragma unroll
                for (int j = 0; j < 4; j++) {
                    #pragma unroll
                    for (int k = 0; k < 5; k++) {
                        acc[2 * j]     = ffma2(P[j + k], W[k],     acc[2 * j]);
                        acc[2 * j + 1] = ffma2(P[j + k], W[5 + k], acc[2 * j + 1]);
                    }
                }
                // group of 4 outputs (x-pairs j=0..1), reuses P[4..9]
                #pragma unroll
                for (int j = 0; j < 2; j++) {
                    #pragma unroll
                    for (int k = 0; k < 5; k++) {
                        acc[8 + 2 * j]     = ffma2(P[4 + j + k], W[k],     acc[8 + 2 * j]);
                        acc[8 + 2 * j + 1] = ffma2(P[4 + j + k], W[5 + k], acc[8 + 2 * j + 1]);
                    }
                }
            }

            // horizontal add + bias, vectorized store (3 x float4)
            #pragma unroll
            for (int u = 0; u < 12; u += 4) {
                float2 a0 = *reinterpret_cast<float2*>(&acc[u + 0]);
                float2 a1 = *reinterpret_cast<float2*>(&acc[u + 1]);
                float2 a2 = *reinterpret_cast<float2*>(&acc[u + 2]);
                float2 a3 = *reinterpret_cast<float2*>(&acc[u + 3]);
                float4 r = make_float4(a0.x + a0.y + bias,
                                       a1.x + a1.y + bias,
                                       a2.x + a2.y + bias,
                                       a3.x + a3.y + bias);
                *reinterpret_cast<float4*>(op + cb0 + u) = r;
            }
        }
    }
}

extern "C" void kernel_launch(void* const* d_in, const int* in_sizes, int n_in,
                              void* d_out, int out_size)
{
    const float* nf  = (const float*)d_in[0];   // [10000, 128]
    const int*   adj = (const int*)  d_in[1];   // [10000, 10000]
    const float* cw  = (const float*)d_in[2];   // [128, 9, 9]
    const float* cb  = (const float*)d_in[3];   // [128]
    float*       out = (float*)d_out;           // [10000, 128, 120]

    prep_weights_kernel<<<(INCH * 10 * OUTCH + 127) / 128, 128>>>(cw);
    lgcl_fused_kernel<<<NN, 128>>>(nf, adj, cb, out);
}

// round 16
// speedup vs baseline: 1.3971x; 1.1800x over previous
#include <cuda_runtime.h>
#include <math_constants.h>
#include <cstdint>

#define NN    10000   // nodes
#define D     128     // feature dim
#define TOPK  8
#define DEG   32
#define OUTCH 128
#define INCH  9       // K+1
#define KS    9       // kernel size
#define XOUT  120     // D - K
#define HALF  60      // XOUT/2 : outputs paired (x, x+HALF)
#define NPAIR 68      // interleaved window length: 60 + KS - 1

// Duplicated weight pairs (w,w), layout [c][t][o]:
// warp's 32 consecutive o read 256B contiguous, table 82KB -> L1-hot.
__device__ float2 g_wdup[INCH][KS][OUTCH];

__global__ void prep_weights_kernel(const float* __restrict__ cw)
{
    int idx = blockIdx.x * blockDim.x + threadIdx.x;
    if (idx >= INCH * KS * OUTCH) return;
    int o = idx % OUTCH;
    int t = (idx / OUTCH) % KS;
    int c = idx / (OUTCH * KS);
    float w = cw[(size_t)o * (INCH * KS) + c * KS + t];
    g_wdup[c][t][o] = make_float2(w, w);
}

__device__ __forceinline__ unsigned long long ffma2(unsigned long long a,
                                                    unsigned long long b,
                                                    unsigned long long c)
{
    unsigned long long d;
    asm("fma.rn.f32x2 %0, %1, %2, %3;" : "=l"(d) : "l"(a), "l"(b), "l"(c));
    return d;
}

__global__ __launch_bounds__(128, 6)
void lgcl_fused_kernel(const float* __restrict__ nf,
                       const int*   __restrict__ adj,
                       const float* __restrict__ cb,
                       float*       __restrict__ out)
{
    // interleaved sel: selp[c][i] = (col_i, col_{i+60}), i = 0..67
    __shared__ __align__(16) float2 selp[INCH][NPAIR];
    __shared__ int nbrs[DEG];
    __shared__ int cnt;

    const int n   = blockIdx.x;
    const int tid = threadIdx.x;     // 128 threads

    if (tid == 0) cnt = 0;
    if (tid < DEG) nbrs[tid] = 0;
    __syncthreads();

    // ---- Phase A: scan adjacency row (MLP 4), compact neighbor indices ----
    {
        const int4* row4 = reinterpret_cast<const int4*>(adj + (size_t)n * NN);
        #pragma unroll
        for (int it = 0; it < 5; it++) {
            int4 v[4];
            int  ii[4];
            #pragma unroll
            for (int q = 0; q < 4; q++) {
                int i = tid + it * 512 + q * 128;
                ii[q] = i;
                v[q] = (i < NN / 4) ? row4[i] : make_int4(0, 0, 0, 0);
            }
            #pragma unroll
            for (int q = 0; q < 4; q++) {
                int4 w = v[q];
                if (w.x | w.y | w.z | w.w) {
                    int e = 4 * ii[q];
                    if (w.x) nbrs[atomicAdd(&cnt, 1)] = e + 0;
                    if (w.y) nbrs[atomicAdd(&cnt, 1)] = e + 1;
                    if (w.z) nbrs[atomicAdd(&cnt, 1)] = e + 2;
                    if (w.w) nbrs[atomicAdd(&cnt, 1)] = e + 3;
                }
            }
        }
    }
    __syncthreads();
    const int m = cnt;   // number of real neighbors (<= 32)

    // ---- Phase B: per-column top-8, write interleaved pairs directly ----
    {
        const int d = tid;           // column index, 0..127
        float v[DEG];
        #pragma unroll
        for (int j = 0; j < DEG; j++)
            v[j] = (j < m) ? nf[(size_t)nbrs[j] * D + d] : -CUDART_INF_F;

        float tk[TOPK];
        #pragma unroll
        for (int s = 0; s < TOPK; s++) tk[s] = -CUDART_INF_F;

        #pragma unroll
        for (int j = 0; j < DEG; j++) {
            float x = v[j];
            #pragma unroll
            for (int s = 0; s < TOPK; s++) {
                float hi = fmaxf(tk[s], x);
                x        = fminf(tk[s], x);
                tk[s]    = hi;
            }
        }
        // torch zero-pads missing neighbors before topk: insert (8-m) zeros
        for (int z = m; z < TOPK; z++) {
            float x = 0.0f;
            #pragma unroll
            for (int s = 0; s < TOPK; s++) {
                float hi = fmaxf(tk[s], x);
                x        = fminf(tk[s], x);
                tk[s]    = hi;
            }
        }

        float colv[INCH];
        colv[0] = nf[(size_t)n * D + d];      // self feature
        #pragma unroll
        for (int s = 0; s < TOPK; s++) colv[1 + s] = tk[s];

        if (d < NPAIR) {
            #pragma unroll
            for (int c = 0; c < INCH; c++) selp[c][d].x = colv[c];
        }
        if (d >= HALF) {
            #pragma unroll
            for (int c = 0; c < INCH; c++) selp[c][d - HALF].y = colv[c];
        }
    }
    __syncthreads();

    // ---- Phase C: Conv1d, far-pair packed f32x2 ----
    // acc pair p computes (out[p], out[p+60]):
    //   acc[p] += selp[c][p+t] * (w_{c,t}, w_{c,t})
    {
        const int o = tid;           // output channel
        const float bias = cb[o];
        float* op = out + ((size_t)n * OUTCH + o) * XOUT;

        for (int pb = 0; pb < HALF; pb += 12) {         // 5 chunks of 12 pairs
            unsigned long long acc[12];
            #pragma unroll
            for (int u = 0; u < 12; u++) acc[u] = 0ull;

            for (int c = 0; c < INCH; c++) {
                unsigned long long W[KS];
                #pragma unroll
                for (int t = 0; t < KS; t++)
                    W[t] = *reinterpret_cast<const unsigned long long*>(&g_wdup[c][t][o]);

                const unsigned long long* S =
                    reinterpret_cast<const unsigned long long*>(&selp[c][0]);

                unsigned long long P[20];
                #pragma unroll
                for (int i = 0; i < 14; i++) P[i] = S[pb + i];
                #pragma unroll
                for (int p = 0; p < 6; p++) {
                    #pragma unroll
                    for (int t = 0; t < KS; t++)
                        acc[p] = ffma2(P[p + t], W[t], acc[p]);
                }
                #pragma unroll
                for (int i = 14; i < 20; i++) P[i] = S[pb + i];
                #pragma unroll
                for (int p = 6; p < 12; p++) {
                    #pragma unroll
                    for (int t = 0; t < KS; t++)
                        acc[p] = ffma2(P[p + t], W[t], acc[p]);
                }
            }

            // split pairs: x-halves -> op[pb..pb+11], y-halves -> op[pb+60..]
            float lo[12], hi[12];
            #pragma unroll
            for (int u = 0; u < 12; u++) {
                float2 a = *reinterpret_cast<float2*>(&acc[u]);
                lo[u] = a.x + bias;
                hi[u] = a.y + bias;
            }
            #pragma unroll
            for (int u = 0; u < 12; u += 4) {
                *reinterpret_cast<float4*>(op + pb + u) =
                    make_float4(lo[u], lo[u + 1], lo[u + 2], lo[u + 3]);
                *reinterpret_cast<float4*>(op + pb + HALF + u) =
                    make_float4(hi[u], hi[u + 1], hi[u + 2], hi[u + 3]);
            }
        }
    }
}

extern "C" void kernel_launch(void* const* d_in, const int* in_sizes, int n_in,
                              void* d_out, int out_size)
{
    const float* nf  = (const float*)d_in[0];   // [10000, 128]
    const int*   adj = (const int*)  d_in[1];   // [10000, 10000]
    const float* cw  = (const float*)d_in[2];   // [128, 9, 9]
    const float* cb  = (const float*)d_in[3];   // [128]
    float*       out = (float*)d_out;           // [10000, 128, 120]

    prep_weights_kernel<<<(INCH * KS * OUTCH + 127) / 128, 128>>>(cw);
    lgcl_fused_kernel<<<NN, 128>>>(nf, adj, cb, out);
}